// round 16
// baseline (speedup 1.0000x reference)
#include <cuda_runtime.h>
#include <cuda_fp16.h>
#include <cuda_bf16.h>
#include <cstdint>

// ---------------- problem constants ----------------
#define L_SEQ 512
#define B_N   256
#define E_DIM 128
#define H_DIM 128
#define G4    512     // 4*H
#define V_SZ  32000
#define T_TAG 48
#define NB    4       // batch lanes per LSTM CTA (half of mma N=8 tile)

typedef unsigned long long ull;

// ---------------- scratch (device globals; no allocation allowed) ----------------
// g_xw layout: [v][dir][j*4+q] where gate (q*128+j) of direction dir.
__device__ __nv_bfloat16 g_xw[(size_t)V_SZ * 1024];            // 64 MiB
__device__ __nv_bfloat16 g_hcat[(size_t)L_SEQ * B_N * 256];    // 64 MiB [l][b][2H]
__device__ float g_emis[(size_t)L_SEQ * B_N * T_TAG];          // 24 MiB
__device__ float g_llh[B_N];
__device__ int   g_crf_ctr;                                    // zero-init; reset each run

// ---------------- generic helpers ----------------
__device__ __forceinline__ float tanh_fast(float x) {
    float y;
    asm("tanh.approx.f32 %0, %1;" : "=f"(y) : "f"(x));
    return y;
}
__device__ __forceinline__ float sig_fast(float x) {
    return fmaf(0.5f, tanh_fast(0.5f * x), 0.5f);
}
__device__ __forceinline__ uint32_t smem_u32(const void* p) {
    uint32_t a;
    asm("{ .reg .u64 t; cvta.to.shared.u64 t, %1; cvt.u32.u64 %0, t; }" : "=r"(a) : "l"(p));
    return a;
}
__device__ __forceinline__ uint32_t bf2(float x, float y) {
    __nv_bfloat162 t = __floats2bfloat162_rn(x, y);
    return *(uint32_t*)&t;
}
__device__ __forceinline__ void ffma2(ull& d, ull a, ull b) {
    asm("fma.rn.f32x2 %0, %1, %2, %0;" : "+l"(d) : "l"(a), "l"(b));
}
__device__ __forceinline__ float2 unpack2(ull v) {
    float2 r;
    asm("mov.b64 {%0, %1}, %2;" : "=f"(r.x), "=f"(r.y) : "l"(v));
    return r;
}
__device__ __forceinline__ void mma_bf16(float* d, const uint32_t* a, const uint32_t* b) {
    asm volatile(
        "mma.sync.aligned.m16n8k16.row.col.f32.bf16.bf16.f32 "
        "{%0,%1,%2,%3}, {%4,%5,%6,%7}, {%8,%9}, {%0,%1,%2,%3};"
        : "+f"(d[0]), "+f"(d[1]), "+f"(d[2]), "+f"(d[3])
        : "r"(a[0]), "r"(a[1]), "r"(a[2]), "r"(a[3]), "r"(b[0]), "r"(b[1]));
}
__device__ __forceinline__ void ldmatrix_x2_trans(uint32_t* r, uint32_t addr) {
    asm volatile("ldmatrix.sync.aligned.m8n8.x2.trans.shared.b16 {%0,%1}, [%2];"
                 : "=r"(r[0]), "=r"(r[1]) : "r"(addr));
}
__device__ __forceinline__ void ldsm_x4(uint32_t* r, uint32_t a) {
    asm volatile("ldmatrix.sync.aligned.m8n8.x4.shared.b16 {%0,%1,%2,%3}, [%4];"
                 : "=r"(r[0]), "=r"(r[1]), "=r"(r[2]), "=r"(r[3]) : "r"(a));
}
__device__ __forceinline__ void ldsm_x2(uint32_t* r, uint32_t a) {
    asm volatile("ldmatrix.sync.aligned.m8n8.x2.shared.b16 {%0,%1}, [%2];"
                 : "=r"(r[0]), "=r"(r[1]) : "r"(a));
}
__device__ __forceinline__ void cp16(uint32_t dst, const void* src) {
    asm volatile("cp.async.ca.shared.global [%0], [%1], 16;" :: "r"(dst), "l"(src));
}
__device__ __forceinline__ float warp_sum(float v) {
#pragma unroll
    for (int o = 16; o; o >>= 1) v += __shfl_xor_sync(0xFFFFFFFFu, v, o);
    return v;
}

// ============================================================================
// Kernel 1: xw table, gate-interleaved output layout.
// Tile n-index nb in [0,8): dir = nb>>2, j0 = (nb&3)*32.
// B tile row r (0..127) <- gate (r&3)*128 + j0 + (r>>2) of direction dir;
// output column (local r) lands at dir*512 + j0*4 + r  (contiguous).
// ============================================================================
#define XPM_A_OFF    0
#define XPM_B_OFF    (128 * 136 * 2)
#define XPM_BIAS_OFF (2 * 128 * 136 * 2)
#define XPM_SMEM     (XPM_BIAS_OFF + 128 * 4)

__global__ __launch_bounds__(256) void xw_mma_kernel(
    const float* __restrict__ emb,
    const float* __restrict__ Wih_f, const float* __restrict__ bih_f,
    const float* __restrict__ bhh_f, const float* __restrict__ Wih_b,
    const float* __restrict__ bih_b, const float* __restrict__ bhh_b) {
    extern __shared__ char xsm[];
    __nv_bfloat16* A_s = (__nv_bfloat16*)(xsm + XPM_A_OFF);   // [128][136]
    __nv_bfloat16* B_s = (__nv_bfloat16*)(xsm + XPM_B_OFF);   // [128][136]
    float* bias_s      = (float*)(xsm + XPM_BIAS_OFF);        // [128]

    const int row0 = blockIdx.y * 128;        // vocab row
    const int nb   = blockIdx.x;              // 0..7
    const int dir  = nb >> 2;
    const int j0   = (nb & 3) * 32;
    const int ocol0 = dir * 512 + j0 * 4;     // output column base
    const int tid  = threadIdx.x;

    const float* Wih = dir ? Wih_b : Wih_f;
    const float* b1  = dir ? bih_b : bih_f;
    const float* b2  = dir ? bhh_b : bhh_f;

    if (tid < 128) {
        const int g = (tid & 3) * 128 + j0 + (tid >> 2);
        bias_s[tid] = b1[g] + b2[g];
    }

    // A: emb rows -> bf16 [r][k], 136-elem row pad
    {
        const int r = tid >> 1, hf = tid & 1;
        const float4* src = (const float4*)(emb + (size_t)(row0 + r) * E_DIM + hf * 64);
        __nv_bfloat16* dst = A_s + r * 136 + hf * 64;
#pragma unroll
        for (int i = 0; i < 8; ++i) {
            float4 v0 = src[2 * i], v1 = src[2 * i + 1];
            uint4 pk;
            pk.x = bf2(v0.x, v0.y);
            pk.y = bf2(v0.z, v0.w);
            pk.z = bf2(v1.x, v1.y);
            pk.w = bf2(v1.z, v1.w);
            *(uint4*)(dst + i * 8) = pk;
        }
    }
    // B: permuted gate rows -> bf16 [n][k]
    {
        const int r = tid >> 1, hf = tid & 1;
        const int g = (r & 3) * 128 + j0 + (r >> 2);
        const float4* src = (const float4*)(Wih + (size_t)g * E_DIM + hf * 64);
        __nv_bfloat16* dst = B_s + r * 136 + hf * 64;
#pragma unroll
        for (int i = 0; i < 8; ++i) {
            float4 v0 = src[2 * i], v1 = src[2 * i + 1];
            uint4 pk;
            pk.x = bf2(v0.x, v0.y);
            pk.y = bf2(v0.z, v0.w);
            pk.z = bf2(v1.x, v1.y);
            pk.w = bf2(v1.z, v1.w);
            *(uint4*)(dst + i * 8) = pk;
        }
    }
    __syncthreads();

    const uint32_t As = smem_u32(A_s), Bs = smem_u32(B_s);
    const int lane = tid & 31, wid = tid >> 5;
    const int m_base = (wid >> 1) * 32;
    const int n_base = (wid & 1) * 64;

    float d[2][8][4];
#pragma unroll
    for (int mt = 0; mt < 2; ++mt)
#pragma unroll
        for (int nt = 0; nt < 8; ++nt)
#pragma unroll
            for (int c = 0; c < 4; ++c) d[mt][nt][c] = 0.f;

    const int aq = lane >> 3;
    const uint32_t a_row = (uint32_t)((aq & 1) * 8 + (lane & 7));
    const uint32_t a_col = (uint32_t)((aq >> 1) * 16);
    const uint32_t b_row = (uint32_t)(lane & 7);
    const uint32_t b_col = (uint32_t)(((lane >> 3) & 1) * 16);

#pragma unroll
    for (int ks = 0; ks < 8; ++ks) {
        uint32_t a0[4], a1[4];
        ldsm_x4(a0, As + (m_base + 0 + a_row) * 272 + ks * 32 + a_col);
        ldsm_x4(a1, As + (m_base + 16 + a_row) * 272 + ks * 32 + a_col);
#pragma unroll
        for (int nt = 0; nt < 8; ++nt) {
            uint32_t bb[2];
            ldsm_x2(bb, Bs + (n_base + nt * 8 + b_row) * 272 + ks * 32 + b_col);
            mma_bf16(d[0][nt], a0, bb);
            mma_bf16(d[1][nt], a1, bb);
        }
    }

    const int r = lane >> 2, c = (lane & 3) * 2;
#pragma unroll
    for (int mt = 0; mt < 2; ++mt) {
        const int gr = row0 + m_base + mt * 16 + r;
#pragma unroll
        for (int nt = 0; nt < 8; ++nt) {
            const int gc = n_base + nt * 8 + c;
            const float bx = bias_s[gc], by = bias_s[gc + 1];
            *(uint32_t*)(g_xw + (size_t)gr * 1024 + ocol0 + gc) =
                bf2(d[mt][nt][0] + bx, d[mt][nt][1] + by);
            *(uint32_t*)(g_xw + (size_t)(gr + 8) * 1024 + ocol0 + gc) =
                bf2(d[mt][nt][2] + bx, d[mt][nt][3] + by);
        }
    }
}

// ============================================================================
// Kernel 2: HMMA LSTM, x gathered from g_xw[word] (interleaved layout):
// one LDS.64 per (h,b) yields all four gate preactivations.
// 256 threads, NB=4 batch/CTA (128 CTAs -> 1/SM), 4-buffer cp.async staging.
// XB_STRIDE = 528 (S mod 32 == 16) -> batch rows land on disjoint bank halves.
// ============================================================================
#define LSTM_HBUF   0
#define LSTM_XBUF   4096
#define XB_STRIDE   528                       // bf16 units per batch row
#define XB_BUFSZ    (4 * XB_STRIDE)           // bf16 units per buffer
#define LSTM_WOFF   (4096 + 4 * XB_BUFSZ * 2)
#define LSTM_SMEM   (LSTM_WOFF + 4 * L_SEQ * 4)

__global__ __launch_bounds__(256) void lstm_mma_kernel(const float* __restrict__ Whh_f,
                                                       const float* __restrict__ Whh_b,
                                                       const int* __restrict__ words) {
    extern __shared__ char smraw[];
    uint32_t* hbuf      = (uint32_t*)(smraw + LSTM_HBUF);       // [2][128][4 bf16x2]
    __nv_bfloat16* xbuf = (__nv_bfloat16*)(smraw + LSTM_XBUF);  // [4][4][528]
    int* w_s            = (int*)(smraw + LSTM_WOFF);            // [4][512]

    const int tid  = threadIdx.x;
    const int lane = tid & 31;
    const int wid  = tid >> 5;
    const int gid  = lane >> 2;
    const int tig  = lane & 3;
    const int dir  = blockIdx.y;
    const int b0   = blockIdx.x * NB;
    const float* Whh = dir ? Whh_b : Whh_f;
    __nv_bfloat16* hout = g_hcat + dir * 128;

    const uint32_t hb_u32 = smem_u32(hbuf);
    const uint32_t xb_u32 = smem_u32(xbuf);
    const bool live = (tig < 2);   // batches 2*tig, 2*tig+1 in [0,4)

    // word indices for the 4 batch rows (contiguous 2048 ints)
    {
        const int4* wsrc = (const int4*)(words + (size_t)b0 * L_SEQ);
        for (int i = tid; i < 512; i += 256) ((int4*)w_s)[i] = wsrc[i];
    }

    uint32_t afr[4][8][4];
#pragma unroll
    for (int q = 0; q < 4; ++q) {
        const int r0 = 16 * wid + 128 * q + gid;
#pragma unroll
        for (int ks = 0; ks < 8; ++ks) {
            const int cc = ks * 16 + 2 * tig;
            float2 v00 = *(const float2*)(Whh + (size_t)r0 * 128 + cc);
            float2 v10 = *(const float2*)(Whh + (size_t)(r0 + 8) * 128 + cc);
            float2 v01 = *(const float2*)(Whh + (size_t)r0 * 128 + cc + 8);
            float2 v11 = *(const float2*)(Whh + (size_t)(r0 + 8) * 128 + cc + 8);
            afr[q][ks][0] = bf2(v00.x, v00.y);
            afr[q][ks][1] = bf2(v10.x, v10.y);
            afr[q][ks][2] = bf2(v01.x, v01.y);
            afr[q][ks][3] = bf2(v11.x, v11.y);
        }
    }

    for (int i = tid; i < 2 * 128 * 4; i += 256) hbuf[i] = 0;
    __syncthreads();   // w_s + hbuf ready

    // prologue: prefetch x(0..2) — 256 x 16B per buffer (1 cp16/thread)
#pragma unroll
    for (int ps = 0; ps < 3; ++ps) {
        const int l = dir ? (L_SEQ - 1 - ps) : ps;
        const int brow = tid >> 6, c16 = tid & 63;
        const int w = w_s[brow * L_SEQ + l];
        cp16(xb_u32 + (uint32_t)(ps * XB_BUFSZ * 2 + brow * XB_STRIDE * 2 + c16 * 16),
             g_xw + (size_t)w * 1024 + dir * 512 + c16 * 8);
        asm volatile("cp.async.commit_group;");
    }
    asm volatile("cp.async.wait_group 2;");   // x(0) ready
    __syncthreads();

    float cst[4] = {0.f, 0.f, 0.f, 0.f};

    for (int s = 0; s < L_SEQ; ++s) {
        const int l = dir ? (L_SEQ - 1 - s) : s;

        // issue prefetch x(s+3) (group always committed to keep the count)
        if (s + 3 < L_SEQ) {
            const int lf = dir ? (L_SEQ - 4 - s) : (s + 3);
            const uint32_t dbase = xb_u32 + (uint32_t)(((s + 3) & 3) * XB_BUFSZ * 2);
            const int brow = tid >> 6, c16 = tid & 63;
            const int w = w_s[brow * L_SEQ + lf];
            cp16(dbase + (uint32_t)(brow * XB_STRIDE * 2 + c16 * 16),
                 g_xw + (size_t)w * 1024 + dir * 512 + c16 * 8);
        }
        asm volatile("cp.async.commit_group;");

        uint32_t rb[8][2];
        const uint32_t base = hb_u32 + (uint32_t)((s & 1) * 2048) + ((uint32_t)(lane & 15) << 4);
#pragma unroll
        for (int ks = 0; ks < 8; ++ks) ldmatrix_x2_trans(rb[ks], base + ks * 256);

        float d[4][4];
#pragma unroll
        for (int q = 0; q < 4; ++q)
#pragma unroll
            for (int c = 0; c < 4; ++c) d[q][c] = 0.f;
#pragma unroll
        for (int ks = 0; ks < 8; ++ks)
#pragma unroll
            for (int q = 0; q < 4; ++q) mma_bf16(d[q], afr[q][ks], rb[ks]);

        // activations: one LDS.64 per (h,b) gives (i,f,g,o) preactivations
        const __nv_bfloat16* xb_base = xbuf + (s & 3) * XB_BUFSZ;
        float hv[4];
#pragma unroll
        for (int p = 0; p < 4; ++p) {
            const int br = (2 * tig + (p & 1)) & 3;
            const int h = 16 * wid + gid + 8 * (p >> 1);
            uint2 u = *(const uint2*)(xb_base + br * XB_STRIDE + h * 4);
            float2 xif = __bfloat1622float2(*(__nv_bfloat162*)&u.x);
            float2 xgo = __bfloat1622float2(*(__nv_bfloat162*)&u.y);
            float gi = d[0][p] + xif.x;
            float gf = d[1][p] + xif.y;
            float gg = d[2][p] + xgo.x;
            float go = d[3][p] + xgo.y;
            float cn = sig_fast(gf) * cst[p] + sig_fast(gi) * tanh_fast(gg);
            cst[p] = cn;
            hv[p] = sig_fast(go) * tanh_fast(cn);
        }

        if (live) {
            const int r0 = 16 * wid + gid;
            hbuf[((s + 1) & 1) * 512 + r0 * 4 + tig]       = bf2(hv[0], hv[1]);
            hbuf[((s + 1) & 1) * 512 + (r0 + 8) * 4 + tig] = bf2(hv[2], hv[3]);

            const size_t orow = ((size_t)l * B_N + b0 + 2 * tig) * 256;
            hout[orow + r0]           = __float2bfloat16(hv[0]);
            hout[orow + 256 + r0]     = __float2bfloat16(hv[1]);
            hout[orow + r0 + 8]       = __float2bfloat16(hv[2]);
            hout[orow + 256 + r0 + 8] = __float2bfloat16(hv[3]);
        }

        asm volatile("cp.async.wait_group 2;");   // x(s+1) ready
        __syncthreads();
    }
}

// ============================================================================
// Kernel 3: emis via HMMA. M=128 rows, N=48 tags, K=256. (unchanged)
// ============================================================================
#define EMM_A_OFF    0
#define EMM_B_OFF    (128 * 264 * 2)
#define EMM_BIAS_OFF (EMM_B_OFF + 48 * 264 * 2)
#define EMM_SMEM     (EMM_BIAS_OFF + 48 * 4)

__global__ __launch_bounds__(256) void emis_mma_kernel(const float* __restrict__ Wout,
                                                       const float* __restrict__ bout) {
    extern __shared__ char esm[];
    __nv_bfloat16* A_s = (__nv_bfloat16*)(esm + EMM_A_OFF);   // [128][264]
    __nv_bfloat16* B_s = (__nv_bfloat16*)(esm + EMM_B_OFF);   // [48][264]
    float* bias_s      = (float*)(esm + EMM_BIAS_OFF);        // [48]

    const int tid = threadIdx.x;
    const int row0 = blockIdx.x * 128;

    if (tid < 48) bias_s[tid] = bout[tid];

    {
        const int r = tid >> 1, hf = tid & 1;
        const uint4* src = (const uint4*)(g_hcat + (size_t)(row0 + r) * 256 + hf * 128);
        uint4* dst = (uint4*)(A_s + r * 264 + hf * 128);
#pragma unroll
        for (int i = 0; i < 16; ++i) dst[i] = src[i];
    }
    if (tid < 96) {
        const int r = tid >> 1, hf = tid & 1;
        const float4* src = (const float4*)(Wout + (size_t)r * 256 + hf * 128);
        __nv_bfloat16* dst = B_s + r * 264 + hf * 128;
#pragma unroll
        for (int i = 0; i < 16; ++i) {
            float4 v0 = src[2 * i], v1 = src[2 * i + 1];
            uint4 pk;
            pk.x = bf2(v0.x, v0.y);
            pk.y = bf2(v0.z, v0.w);
            pk.z = bf2(v1.x, v1.y);
            pk.w = bf2(v1.z, v1.w);
            *(uint4*)(dst + i * 8) = pk;
        }
    }
    __syncthreads();

    const uint32_t As = smem_u32(A_s), Bs = smem_u32(B_s);
    const int lane = tid & 31, wid = tid >> 5;
    const int m_base = (wid >> 1) * 32;
    const int n_base = (wid & 1) * 24;

    const int aq = lane >> 3;
    const uint32_t a_row = (uint32_t)((aq & 1) * 8 + (lane & 7));
    const uint32_t a_col = (uint32_t)((aq >> 1) * 16);
    const uint32_t b_row = (uint32_t)(lane & 7);
    const uint32_t b_col = (uint32_t)(((lane >> 3) & 1) * 16);

    float d[2][3][4];
#pragma unroll
    for (int mt = 0; mt < 2; ++mt)
#pragma unroll
        for (int nt = 0; nt < 3; ++nt)
#pragma unroll
            for (int c = 0; c < 4; ++c) d[mt][nt][c] = 0.f;

#pragma unroll
    for (int ks = 0; ks < 16; ++ks) {
        uint32_t a0[4], a1[4];
        ldsm_x4(a0, As + (m_base + 0 + a_row) * 528 + ks * 32 + a_col);
        ldsm_x4(a1, As + (m_base + 16 + a_row) * 528 + ks * 32 + a_col);
#pragma unroll
        for (int nt = 0; nt < 3; ++nt) {
            uint32_t bb[2];
            ldsm_x2(bb, Bs + (n_base + nt * 8 + b_row) * 528 + ks * 32 + b_col);
            mma_bf16(d[0][nt], a0, bb);
            mma_bf16(d[1][nt], a1, bb);
        }
    }

    const int r = lane >> 2, c = (lane & 3) * 2;
#pragma unroll
    for (int mt = 0; mt < 2; ++mt) {
        const int gr = row0 + m_base + mt * 16 + r;
#pragma unroll
        for (int nt = 0; nt < 3; ++nt) {
            const int gc = n_base + nt * 8 + c;
            const float bx = bias_s[gc], by = bias_s[gc + 1];
            float2 o0 = make_float2(d[mt][nt][0] + bx, d[mt][nt][1] + by);
            float2 o1 = make_float2(d[mt][nt][2] + bx, d[mt][nt][3] + by);
            *(float2*)(g_emis + (size_t)gr * T_TAG + gc) = o0;
            *(float2*)(g_emis + (size_t)(gr + 8) * T_TAG + gc) = o1;
        }
    }
}

// ============================================================================
// Kernel 4: CRF (R14/R15 form: fwd/bwd split, reg-hoisted E row, renorm/8,
// fused final reduction).
// ============================================================================
__global__ __launch_bounds__(128, 1) void crf_kernel(const int* __restrict__ words,
                                                     const int* __restrict__ tags,
                                                     const float* __restrict__ trans,
                                                     const float* __restrict__ start_trans,
                                                     const float* __restrict__ end_trans,
                                                     float* __restrict__ out) {
    __shared__ __align__(16) float Efw_s[48 * 52];
    __shared__ __align__(16) float Ebw_s[48 * 52];
    __shared__ __align__(16) float tr_s[48 * 48];
    __shared__ __align__(16) float x_s[4][48];
    __shared__ float lz_s[4];
    __shared__ float np_s[4];
    __shared__ int last_s;

    const int tid = threadIdx.x;
    const int wid = tid >> 5, lane = tid & 31;
    const int role = wid & 1;            // 0 = forward, 1 = backward
    const int b = blockIdx.x * 2 + (wid >> 1);

    for (int idx = tid; idx < 48 * 48; idx += 128) {
        float v = trans[idx];
        tr_s[idx] = v;
        float e = __expf(v);
        const int i = idx / 48, j = idx - i * 48;
        Efw_s[j * 52 + i] = e;
        Ebw_s[i * 52 + j] = e;
    }
    __syncthreads();

    // sequence length (prefix mask == words != 0)
    int cnt = 0;
    for (int l = lane; l < L_SEQ; l += 32) cnt += (words[b * L_SEQ + l] != 0) ? 1 : 0;
#pragma unroll
    for (int o = 16; o; o >>= 1) cnt += __shfl_xor_sync(0xFFFFFFFFu, cnt, o);
    const int len = cnt;
    const int c = len >> 1;

    const int j1 = lane;
    const int j2 = 32 + lane;
    const bool has2 = lane < 16;

    // hoist this lane's own E row (j1) into registers: 24 ull = 48 floats
    ull e1r[24];
    {
        const ull* src = (const ull*)((role ? Ebw_s : Efw_s) + j1 * 52);
#pragma unroll
        for (int i = 0; i < 24; ++i) e1r[i] = src[i];
    }
    const ulonglong2* m2 = (const ulonglong2*)((role ? Ebw_s : Efw_s) + j2 * 52);

    // ---- numerator partial ----
    {
        const int lo = role ? (c + 1) : 1;
        const int hi = role ? len : (c + 1);
        float np = 0.f;
        for (int l = lo + lane; l < hi; l += 32) {
            int tp = tags[b * L_SEQ + l - 1];
            int tc = tags[b * L_SEQ + l];
            np += tr_s[tp * 48 + tc] + g_emis[((size_t)l * B_N + b) * T_TAG + tc];
        }
        np = warp_sum(np);
        if (lane == 0) {
            if (role == 0) {
                int t0 = tags[b * L_SEQ];
                np += start_trans[t0] + g_emis[(size_t)b * T_TAG + t0];
            } else {
                np += end_trans[tags[b * L_SEQ + (len - 1)]];
            }
            np_s[wid] = np;
        }
    }

    // ---- init vector ----
    float p1, p2, logZ = 0.f;
    if (role == 0) {
        p1 = __expf(start_trans[j1] + g_emis[(size_t)b * T_TAG + j1]);
        p2 = has2 ? __expf(start_trans[j2] + g_emis[(size_t)b * T_TAG + j2]) : 0.f;
    } else {
        p1 = __expf(end_trans[j1]);
        p2 = has2 ? __expf(end_trans[j2]) : 0.f;
    }

    const int nsteps = role ? (len - 1 - c) : c;

    // emission position for step t: fwd -> 1+t, bwd -> len-1-t.  4-deep pipeline.
    float e1p0 = 0.f, e1p1 = 0.f, e1p2 = 0.f, e1p3 = 0.f;
    float e2p0 = 0.f, e2p1 = 0.f, e2p2 = 0.f, e2p3 = 0.f;
#pragma unroll
    for (int k = 0; k < 4; ++k) {
        float v1 = 0.f, v2 = 0.f;
        if (k < nsteps) {
            const int ei = role ? (len - 1 - k) : (1 + k);
            const size_t eb = ((size_t)ei * B_N + b) * T_TAG;
            v1 = g_emis[eb + j1];
            v2 = has2 ? g_emis[eb + j2] : 0.f;
        }
        if (k == 0) { e1p0 = v1; e2p0 = v2; }
        else if (k == 1) { e1p1 = v1; e2p1 = v2; }
        else if (k == 2) { e1p2 = v1; e2p2 = v2; }
        else { e1p3 = v1; e2p3 = v2; }
    }

    for (int t = 0; t < nsteps; ++t) {
        // prefetch emission for t+4
        float ft1 = 0.f, ft2 = 0.f;
        if (t + 4 < nsteps) {
            const int ei = role ? (len - 5 - t) : (5 + t);
            const size_t eb = ((size_t)ei * B_N + b) * T_TAG;
            ft1 = g_emis[eb + j1];
            ft2 = has2 ? g_emis[eb + j2] : 0.f;
        }

        float x1, x2;
        if (role == 0) {
            x1 = p1;
            x2 = p2;
        } else {
            x1 = p1 * __expf(e1p0);
            x2 = has2 ? p2 * __expf(e2p0) : 0.f;
        }
        x_s[wid][j1] = x1;
        if (has2) x_s[wid][j2] = x2;
        __syncwarp();

        // matvec: j1 from register E row, j2 from smem
        ull A0 = 0ull, A1 = 0ull, B0 = 0ull, B1 = 0ull;
        const ulonglong2* px = (const ulonglong2*)x_s[wid];
#pragma unroll
        for (int i4 = 0; i4 < 12; ++i4) {
            ulonglong2 pv = px[i4];
            ffma2(A0, pv.x, e1r[2 * i4]);
            ffma2(A1, pv.y, e1r[2 * i4 + 1]);
            if (has2) {
                ulonglong2 mv2 = m2[i4];
                ffma2(B0, pv.x, mv2.x);
                ffma2(B1, pv.y, mv2.y);
            }
        }
        float2 a0 = unpack2(A0), a1 = unpack2(A1);
        float s1 = (a0.x + a0.y) + (a1.x + a1.y);
        float s2;
        {
            float2 b0v = unpack2(B0), b1v = unpack2(B1);
            s2 = (b0v.x + b0v.y) + (b1v.x + b1v.y);
        }

        if (role == 0) {
            p1 = s1 * __expf(e1p0);
            p2 = has2 ? s2 * __expf(e2p0) : 0.f;
        } else {
            p1 = s1;
            p2 = has2 ? s2 : 0.f;
        }
        // shift emission pipeline
        e1p0 = e1p1; e1p1 = e1p2; e1p2 = e1p3; e1p3 = ft1;
        e2p0 = e2p1; e2p1 = e2p2; e2p2 = e2p3; e2p3 = ft2;

        // renorm every 8 steps (growth/step <= ~1e4 -> 8 steps ~1e32 << fp32 max)
        if ((t & 7) == 7) {
            float S = warp_sum(p1 + p2);
            float inv = 1.f / S;
            p1 *= inv;
            p2 *= inv;
            logZ += __logf(S);
        }
        __syncwarp();
    }

    x_s[wid][j1] = p1;
    if (has2) x_s[wid][j2] = p2;
    if (lane == 0) lz_s[wid] = logZ;
    __syncthreads();

    if (role == 0) {
        float dsum = x_s[wid][j1] * x_s[wid + 1][j1];
        if (has2) dsum += x_s[wid][j2] * x_s[wid + 1][j2];
        dsum = warp_sum(dsum);
        if (lane == 0) {
            float denom = lz_s[wid] + lz_s[wid + 1] + __logf(dsum);
            g_llh[b] = (np_s[wid] + np_s[wid + 1]) - denom;
        }
    }

    // ---- fused final reduction: last CTA computes -mean(llh) ----
    __syncthreads();
    if (tid == 0) {
        __threadfence();
        int prev = atomicAdd(&g_crf_ctr, 1);
        last_s = (prev == (int)gridDim.x - 1) ? 1 : 0;
    }
    __syncthreads();
    if (last_s) {
        __shared__ float red[128];
        float v = g_llh[tid] + g_llh[tid + 128];
        red[tid] = v;
        __syncthreads();
        for (int s = 64; s > 0; s >>= 1) {
            if (tid < s) red[tid] += red[tid + s];
            __syncthreads();
        }
        if (tid == 0) {
            out[0] = -red[0] / (float)B_N;
            g_crf_ctr = 0;   // reset for next (deterministic) run
        }
    }
}

// ============================================================================
// launch
// ============================================================================
extern "C" void kernel_launch(void* const* d_in, const int* in_sizes, int n_in,
                              void* d_out, int out_size) {
    const int*   words  = (const int*)d_in[0];
    const int*   tags   = (const int*)d_in[1];
    // d_in[2] = mask (unused; derived from words != 0)
    const float* emb    = (const float*)d_in[3];
    const float* Wih_f  = (const float*)d_in[4];
    const float* Whh_f  = (const float*)d_in[5];
    const float* bih_f  = (const float*)d_in[6];
    const float* bhh_f  = (const float*)d_in[7];
    const float* Wih_b  = (const float*)d_in[8];
    const float* Whh_b  = (const float*)d_in[9];
    const float* bih_b  = (const float*)d_in[10];
    const float* bhh_b  = (const float*)d_in[11];
    const float* Wout   = (const float*)d_in[12];
    const float* bout   = (const float*)d_in[13];
    const float* trans  = (const float*)d_in[14];
    const float* st     = (const float*)d_in[15];
    const float* et     = (const float*)d_in[16];
    float* out = (float*)d_out;

    cudaFuncSetAttribute(xw_mma_kernel, cudaFuncAttributeMaxDynamicSharedMemorySize,
                         XPM_SMEM);
    cudaFuncSetAttribute(lstm_mma_kernel, cudaFuncAttributeMaxDynamicSharedMemorySize,
                         LSTM_SMEM);
    cudaFuncSetAttribute(emis_mma_kernel, cudaFuncAttributeMaxDynamicSharedMemorySize,
                         EMM_SMEM);

    // 1) vocab-level input projection table (gate-interleaved layout)
    xw_mma_kernel<<<dim3(8, V_SZ / 128), 256, XPM_SMEM>>>(
        emb, Wih_f, bih_f, bhh_f, Wih_b, bih_b, bhh_b);

    // 2) HMMA BiLSTM gathering x rows from g_xw: 64 CTAs x 2 dirs = 128 (1/SM)
    lstm_mma_kernel<<<dim3(B_N / NB, 2), 256, LSTM_SMEM>>>(Whh_f, Whh_b, words);

    // 3) emissions via HMMA
    emis_mma_kernel<<<(L_SEQ * B_N) / 128, 256, EMM_SMEM>>>(Wout, bout);

    // 4) CRF (fused final reduction)
    crf_kernel<<<B_N / 2, 128>>>(words, tags, trans, st, et, out);
}